// round 1
// baseline (speedup 1.0000x reference)
#include <cuda_runtime.h>
#include <math.h>

// Problem constants
#define BB   2
#define SEQ  2048
#define DM   1024
#define NH   16
#define DH   64
#define DFF  4096
#define MR   (BB * SEQ)   // 4096 rows

// ---------------------------------------------------------------------------
// Scratch (no allocations allowed -> __device__ globals)
// ---------------------------------------------------------------------------
__device__ float g_h   [(size_t)MR * DM];        // LN1 output          16 MB
__device__ float g_qkv [(size_t)MR * 3 * DM];    // QKV projection      48 MB
__device__ float g_o   [(size_t)MR * DM];        // attention output    16 MB
__device__ float g_src2[(size_t)MR * DM];        // residual 1          16 MB
__device__ float g_f   [(size_t)MR * DM];        // LN2 output          16 MB
__device__ float g_ffn [(size_t)MR * DFF];       // FFN hidden          64 MB

// ---------------------------------------------------------------------------
// LayerNorm: one block per row of 1024, 256 threads (4 elems/thread)
// ---------------------------------------------------------------------------
__global__ __launch_bounds__(256) void ln_kernel(
    const float* __restrict__ x, const float* __restrict__ g,
    const float* __restrict__ bt, float* __restrict__ y)
{
    int row = blockIdx.x;
    int t = threadIdx.x;
    const float* xr = x + (size_t)row * DM;

    float4 v = *(const float4*)(xr + t * 4);
    float s  = v.x + v.y + v.z + v.w;
    float ss = v.x * v.x + v.y * v.y + v.z * v.z + v.w * v.w;

    #pragma unroll
    for (int o = 16; o; o >>= 1) {
        s  += __shfl_xor_sync(0xffffffffu, s,  o);
        ss += __shfl_xor_sync(0xffffffffu, ss, o);
    }
    __shared__ float rs[8], rss[8];
    if ((t & 31) == 0) { rs[t >> 5] = s; rss[t >> 5] = ss; }
    __syncthreads();
    if (t < 32) {
        float a  = (t < 8) ? rs[t]  : 0.f;
        float bb = (t < 8) ? rss[t] : 0.f;
        #pragma unroll
        for (int o = 4; o; o >>= 1) {
            a  += __shfl_xor_sync(0xffffffffu, a,  o);
            bb += __shfl_xor_sync(0xffffffffu, bb, o);
        }
        if (t == 0) { rs[0] = a; rss[0] = bb; }
    }
    __syncthreads();
    float mean = rs[0] * (1.f / DM);
    float var  = rss[0] * (1.f / DM) - mean * mean;
    float rstd = rsqrtf(var + 1e-5f);

    float4 gv = *(const float4*)(g  + t * 4);
    float4 bv = *(const float4*)(bt + t * 4);
    float4 ov;
    ov.x = (v.x - mean) * rstd * gv.x + bv.x;
    ov.y = (v.y - mean) * rstd * gv.y + bv.y;
    ov.z = (v.z - mean) * rstd * gv.z + bv.z;
    ov.w = (v.w - mean) * rstd * gv.w + bv.w;
    *(float4*)(y + (size_t)row * DM + t * 4) = ov;
}

// ---------------------------------------------------------------------------
// GEMM: C[M,N] = A[M,K] @ W[N,K]^T + bias (+res) (opt relu)
// 128x128 tile, BK=8, 256 threads, 8x8 per thread.
// ---------------------------------------------------------------------------
__global__ __launch_bounds__(256, 2) void gemm_kernel(
    const float* __restrict__ A, const float* __restrict__ W,
    const float* __restrict__ bias, const float* __restrict__ res,
    float* __restrict__ C, int M, int N, int K, int do_relu)
{
    __shared__ float As[8][132];
    __shared__ float Bs[8][132];

    int t  = threadIdx.x;
    int m0 = blockIdx.y * 128;
    int n0 = blockIdx.x * 128;

    int lr = t >> 1;           // 0..127 (tile row for loads)
    int lc = (t & 1) * 4;      // 0 or 4 (k offset for loads)
    const float* Ag = A + (size_t)(m0 + lr) * K + lc;
    const float* Wg = W + (size_t)(n0 + lr) * K + lc;

    int ty = t >> 4;           // 0..15
    int tx = t & 15;           // 0..15

    float acc[8][8];
    #pragma unroll
    for (int i = 0; i < 8; i++)
        #pragma unroll
        for (int j = 0; j < 8; j++) acc[i][j] = 0.f;

    for (int k0 = 0; k0 < K; k0 += 8) {
        float4 av = *(const float4*)(Ag + k0);
        float4 wv = *(const float4*)(Wg + k0);
        __syncthreads();
        As[lc + 0][lr] = av.x; As[lc + 1][lr] = av.y;
        As[lc + 2][lr] = av.z; As[lc + 3][lr] = av.w;
        Bs[lc + 0][lr] = wv.x; Bs[lc + 1][lr] = wv.y;
        Bs[lc + 2][lr] = wv.z; Bs[lc + 3][lr] = wv.w;
        __syncthreads();

        #pragma unroll
        for (int k = 0; k < 8; k++) {
            float4 a0 = *(const float4*)&As[k][ty * 8];
            float4 a1 = *(const float4*)&As[k][ty * 8 + 4];
            float4 b0 = *(const float4*)&Bs[k][tx * 8];
            float4 b1 = *(const float4*)&Bs[k][tx * 8 + 4];
            float a[8] = {a0.x, a0.y, a0.z, a0.w, a1.x, a1.y, a1.z, a1.w};
            float b[8] = {b0.x, b0.y, b0.z, b0.w, b1.x, b1.y, b1.z, b1.w};
            #pragma unroll
            for (int i = 0; i < 8; i++)
                #pragma unroll
                for (int j = 0; j < 8; j++)
                    acc[i][j] += a[i] * b[j];
        }
    }

    #pragma unroll
    for (int i = 0; i < 8; i++) {
        size_t row = (size_t)(m0 + ty * 8 + i);
        float*       Crow = C + row * N + n0 + tx * 8;
        const float* Rrow = res ? (res + row * N + n0 + tx * 8) : nullptr;
        #pragma unroll
        for (int j = 0; j < 8; j++) {
            float v = acc[i][j] + bias[n0 + tx * 8 + j];
            if (Rrow) v += Rrow[j];
            if (do_relu) v = fmaxf(v, 0.f);
            Crow[j] = v;
        }
    }
}

// ---------------------------------------------------------------------------
// Flash-style attention with ALiBi-ish mask.
// qkv layout: [b*SEQ + s][3072], Q at col h*64+d, K at 1024+h*64+d, V at 2048+...
// mask(h,i,j) = -(i+j)*2^-h for j<=i else -inf;  scores = qk/8 + mask
// grid: (S/64=32 q-tiles, B*H=32), 256 threads.
// thread t: row r=t>>2 (query within tile), c4=t&3.
//   scores: 16 cols c = 4*i + c4 ;  PV: 16 dims d = c4*16 + i
// ---------------------------------------------------------------------------
__global__ __launch_bounds__(256, 2) void attn_kernel(
    const float* __restrict__ qkv, float* __restrict__ o)
{
    __shared__ float Ks[64][68];   // K tile; reused to hold P
    __shared__ float Vs[64][68];

    int qt = blockIdx.x;
    int bh = blockIdx.y;
    int b  = bh >> 4;
    int h  = bh & 15;

    const float* base = qkv + ((size_t)b * SEQ) * (3 * DM) + h * DH;

    int t  = threadIdx.x;
    int r  = t >> 2;       // 0..63
    int c4 = t & 3;        // 0..3
    int iq = qt * 64 + r;  // global query index

    // q row (scaled by 1/sqrt(64)=0.125) in registers
    float q[64];
    const float* qp = base + (size_t)iq * (3 * DM);
    #pragma unroll
    for (int d4 = 0; d4 < 16; d4++) {
        float4 v = *(const float4*)(qp + d4 * 4);
        q[d4 * 4 + 0] = v.x * 0.125f;
        q[d4 * 4 + 1] = v.y * 0.125f;
        q[d4 * 4 + 2] = v.z * 0.125f;
        q[d4 * 4 + 3] = v.w * 0.125f;
    }

    float m = -1e30f, l = 0.f;
    float oacc[16];
    #pragma unroll
    for (int i = 0; i < 16; i++) oacc[i] = 0.f;
    float slope = exp2f(-(float)h);

    for (int kt = 0; kt <= qt; kt++) {
        __syncthreads();   // previous iteration done with Ks/Vs
        #pragma unroll
        for (int e = 0; e < 4; e++) {
            int idx = t + 256 * e;       // 0..1023
            int row = idx >> 4;
            int f4  = idx & 15;
            const float* kp = base + (size_t)(kt * 64 + row) * (3 * DM) + DM + f4 * 4;
            *(float4*)&Ks[row][f4 * 4] = *(const float4*)kp;
            *(float4*)&Vs[row][f4 * 4] = *(const float4*)(kp + DM);
        }
        __syncthreads();

        // scores
        float p[16];
        float tmax = -1e30f;
        #pragma unroll
        for (int i = 0; i < 16; i++) {
            int c = 4 * i + c4;
            int j = kt * 64 + c;
            float s = 0.f;
            #pragma unroll
            for (int d4 = 0; d4 < 16; d4++) {
                float4 kv = *(const float4*)&Ks[c][d4 * 4];
                s += q[d4 * 4 + 0] * kv.x + q[d4 * 4 + 1] * kv.y
                   + q[d4 * 4 + 2] * kv.z + q[d4 * 4 + 3] * kv.w;
            }
            s -= (float)(iq + j) * slope;
            if (j > iq) s = -1e30f;
            p[i] = s;
            tmax = fmaxf(tmax, s);
        }
        tmax = fmaxf(tmax, __shfl_xor_sync(0xffffffffu, tmax, 1));
        tmax = fmaxf(tmax, __shfl_xor_sync(0xffffffffu, tmax, 2));

        float mnew = fmaxf(m, tmax);
        float corr = __expf(m - mnew);
        float psum = 0.f;
        #pragma unroll
        for (int i = 0; i < 16; i++) {
            p[i] = __expf(p[i] - mnew);
            psum += p[i];
        }
        psum += __shfl_xor_sync(0xffffffffu, psum, 1);
        psum += __shfl_xor_sync(0xffffffffu, psum, 2);
        l = l * corr + psum;
        m = mnew;
        #pragma unroll
        for (int i = 0; i < 16; i++) oacc[i] *= corr;

        __syncthreads();   // everyone done reading Ks as K
        #pragma unroll
        for (int i = 0; i < 16; i++) Ks[r][4 * i + c4] = p[i];
        __syncthreads();

        // PV: oacc[d], d = c4*16 + dd
        #pragma unroll
        for (int j = 0; j < 64; j++) {
            float pv = Ks[r][j];
            #pragma unroll
            for (int db = 0; db < 4; db++) {
                float4 vv = *(const float4*)&Vs[j][c4 * 16 + db * 4];
                oacc[db * 4 + 0] += pv * vv.x;
                oacc[db * 4 + 1] += pv * vv.y;
                oacc[db * 4 + 2] += pv * vv.z;
                oacc[db * 4 + 3] += pv * vv.w;
            }
        }
    }

    float inv = 1.f / l;
    float* op = o + ((size_t)(b * SEQ) + iq) * DM + h * DH + c4 * 16;
    #pragma unroll
    for (int db = 0; db < 4; db++) {
        float4 ov;
        ov.x = oacc[db * 4 + 0] * inv;
        ov.y = oacc[db * 4 + 1] * inv;
        ov.z = oacc[db * 4 + 2] * inv;
        ov.w = oacc[db * 4 + 3] * inv;
        *(float4*)(op + db * 4) = ov;
    }
}

// ---------------------------------------------------------------------------
// Launch
// ---------------------------------------------------------------------------
extern "C" void kernel_launch(void* const* d_in, const int* in_sizes, int n_in,
                              void* d_out, int out_size)
{
    const float* src   = (const float*)d_in[0];
    const float* ln1_g = (const float*)d_in[1];
    const float* ln1_b = (const float*)d_in[2];
    const float* Wqkv  = (const float*)d_in[3];
    const float* bqkv  = (const float*)d_in[4];
    const float* Wout  = (const float*)d_in[5];
    const float* bout  = (const float*)d_in[6];
    const float* ln2_g = (const float*)d_in[7];
    const float* ln2_b = (const float*)d_in[8];
    const float* W1    = (const float*)d_in[9];
    const float* b1    = (const float*)d_in[10];
    const float* W2    = (const float*)d_in[11];
    const float* b2    = (const float*)d_in[12];
    float* out = (float*)d_out;

    float *h, *qkv, *o, *src2, *f, *ffn;
    cudaGetSymbolAddress((void**)&h,    g_h);
    cudaGetSymbolAddress((void**)&qkv,  g_qkv);
    cudaGetSymbolAddress((void**)&o,    g_o);
    cudaGetSymbolAddress((void**)&src2, g_src2);
    cudaGetSymbolAddress((void**)&f,    g_f);
    cudaGetSymbolAddress((void**)&ffn,  g_ffn);

    // 1) LN1
    ln_kernel<<<MR, 256>>>(src, ln1_g, ln1_b, h);
    // 2) QKV = h @ Wqkv^T + bqkv   [4096, 3072]
    gemm_kernel<<<dim3(3 * DM / 128, MR / 128), 256>>>(
        h, Wqkv, bqkv, nullptr, qkv, MR, 3 * DM, DM, 0);
    // 3) attention -> o  [4096, 1024]
    attn_kernel<<<dim3(SEQ / 64, BB * NH), 256>>>(qkv, o);
    // 4) src2 = src + o @ Wout^T + bout
    gemm_kernel<<<dim3(DM / 128, MR / 128), 256>>>(
        o, Wout, bout, src, src2, MR, DM, DM, 0);
    // 5) LN2
    ln_kernel<<<MR, 256>>>(src2, ln2_g, ln2_b, f);
    // 6) ffn = relu(f @ W1^T + b1)  [4096, 4096]
    gemm_kernel<<<dim3(DFF / 128, MR / 128), 256>>>(
        f, W1, b1, nullptr, ffn, MR, DFF, DM, 1);
    // 7) out = src2 + ffn @ W2^T + b2
    gemm_kernel<<<dim3(DM / 128, MR / 128), 256>>>(
        ffn, W2, b2, src2, out, MR, DM, DFF, 0);
}

// round 3
// speedup vs baseline: 1.7716x; 1.7716x over previous
#include <cuda_runtime.h>
#include <math.h>
#include <stdint.h>

// Problem constants
#define BB   2
#define SEQ  2048
#define DM   1024
#define NH   16
#define DH   64
#define DFF  4096
#define MR   (BB * SEQ)   // 4096 rows

// ---------------------------------------------------------------------------
// Scratch (no allocations allowed -> __device__ globals)
// ---------------------------------------------------------------------------
__device__ float g_h   [(size_t)MR * DM];        // LN1 output (tf32-rounded)
__device__ float g_qkv [(size_t)MR * 3 * DM];    // QKV projection (tf32-rounded)
__device__ float g_o   [(size_t)MR * DM];        // attention output (tf32-rounded)
__device__ float g_src2[(size_t)MR * DM];        // residual 1 (full fp32)
__device__ float g_f   [(size_t)MR * DM];        // LN2 output (tf32-rounded)
__device__ float g_ffn [(size_t)MR * DFF];       // FFN hidden (tf32-rounded)
__device__ float g_wq  [(size_t)3 * DM * DM];    // rounded Wqkv
__device__ float g_wo  [(size_t)DM * DM];        // rounded Wout
__device__ float g_w1  [(size_t)DFF * DM];       // rounded W1
__device__ float g_w2  [(size_t)DM * DFF];       // rounded W2

// ---------------------------------------------------------------------------
// Helpers
// ---------------------------------------------------------------------------
__device__ __forceinline__ uint32_t smem_u32(const void* p) {
    uint32_t a;
    asm("{ .reg .u64 t; cvta.to.shared.u64 t, %1; cvt.u32.u64 %0, t; }" : "=r"(a) : "l"(p));
    return a;
}
__device__ __forceinline__ float rtf32(float x) {
    uint32_t r;
    asm("cvt.rna.tf32.f32 %0, %1;" : "=r"(r) : "f"(x));
    return __uint_as_float(r);
}

#define CP16(dst, src) \
    asm volatile("cp.async.cg.shared.global [%0], [%1], 16;" :: "r"(dst), "l"(src) : "memory")
#define CP_COMMIT()  asm volatile("cp.async.commit_group;" ::: "memory")
#define CP_WAIT(n)   asm volatile("cp.async.wait_group %0;" :: "n"(n) : "memory")

__device__ __forceinline__ void mma_tf32(float* d, const uint32_t* a, const uint32_t* b) {
    asm volatile(
        "mma.sync.aligned.m16n8k8.row.col.f32.tf32.tf32.f32 "
        "{%0,%1,%2,%3}, {%4,%5,%6,%7}, {%8,%9}, {%0,%1,%2,%3};"
        : "+f"(d[0]), "+f"(d[1]), "+f"(d[2]), "+f"(d[3])
        : "r"(a[0]), "r"(a[1]), "r"(a[2]), "r"(a[3]), "r"(b[0]), "r"(b[1]));
}

// ---------------------------------------------------------------------------
// Tensor-core GEMM: C[M,N] = A[M,K] @ W[N,K]^T + bias (+res) (opt relu/round)
// 128x128 tile per CTA, BK=32, double-buffered cp.async, 256 threads.
// Warp layout 2(m) x 4(n): each warp 64x32 via 4x4 m16n8k8 fragments.
// Smem rows padded to 36 floats -> conflict-free fragment LDS.
// flags: 1 = relu, 2 = round output to tf32
// ---------------------------------------------------------------------------
#define SMS    36                 // smem row stride (floats)
#define TILE_F (128 * SMS)        // floats per (A or B) buffer

__global__ __launch_bounds__(256, 2) void mma_gemm(
    const float* __restrict__ A, const float* __restrict__ W,
    const float* __restrict__ bias, const float* __restrict__ res,
    float* __restrict__ C, int N, int K, int flags)
{
    extern __shared__ float sm[];
    float* As = sm;                 // [2][128][36]
    float* Bs = sm + 2 * TILE_F;    // [2][128][36]

    int t    = threadIdx.x;
    int wid  = t >> 5, lane = t & 31;
    int m0   = blockIdx.y * 128, n0 = blockIdx.x * 128;
    int wm   = (wid >> 2) * 64;     // warp m offset
    int wn   = (wid & 3) * 32;      // warp n offset
    int lr   = lane >> 2;           // 0..7
    int lc   = lane & 3;            // 0..3

    // load assignment: row tr + 32*i, 4 floats at col (t&7)*4
    int tr = t >> 3, tc4 = (t & 7) * 4;
    const float* Ag = A + (size_t)(m0 + tr) * K + tc4;
    const float* Wg = W + (size_t)(n0 + tr) * K + tc4;
    uint32_t sA = smem_u32(As) + (uint32_t)((tr * SMS + tc4) * 4);
    uint32_t sB = smem_u32(Bs) + (uint32_t)((tr * SMS + tc4) * 4);
    const uint32_t rowStep = 32 * SMS * 4;       // 32 rows in bytes
    const uint32_t bufStep = TILE_F * 4;         // buffer in bytes

    float acc[4][4][4];
    #pragma unroll
    for (int i = 0; i < 4; i++)
        #pragma unroll
        for (int j = 0; j < 4; j++)
            #pragma unroll
            for (int k = 0; k < 4; k++) acc[i][j][k] = 0.f;

    int NK = K >> 5;

    // prologue: buffer 0 <- k-chunk 0
    #pragma unroll
    for (int i = 0; i < 4; i++) {
        CP16(sA + i * rowStep, Ag + (size_t)(32 * i) * K);
        CP16(sB + i * rowStep, Wg + (size_t)(32 * i) * K);
    }
    CP_COMMIT();

    for (int kt = 0; kt < NK; kt++) {
        int buf = kt & 1;
        // prefetch next chunk into buf^1
        if (kt + 1 < NK) {
            uint32_t off = (uint32_t)(buf ^ 1) * bufStep;
            const float* Ap = Ag + (size_t)(kt + 1) * 32;
            const float* Wp = Wg + (size_t)(kt + 1) * 32;
            #pragma unroll
            for (int i = 0; i < 4; i++) {
                CP16(sA + off + i * rowStep, Ap + (size_t)(32 * i) * K);
                CP16(sB + off + i * rowStep, Wp + (size_t)(32 * i) * K);
            }
            CP_COMMIT();
            CP_WAIT(1);            // current chunk complete
        } else {
            CP_WAIT(0);
        }
        __syncthreads();

        const float* Ab = As + buf * TILE_F;
        const float* Bb = Bs + buf * TILE_F;
        #pragma unroll
        for (int ks = 0; ks < 4; ks++) {
            uint32_t a[4][4], b[4][2];
            #pragma unroll
            for (int mt = 0; mt < 4; mt++) {
                int r = wm + mt * 16 + lr;
                const float* p = Ab + r * SMS + ks * 8 + lc;
                a[mt][0] = __float_as_uint(p[0]);
                a[mt][1] = __float_as_uint(p[8 * SMS]);
                a[mt][2] = __float_as_uint(p[4]);
                a[mt][3] = __float_as_uint(p[8 * SMS + 4]);
            }
            #pragma unroll
            for (int nt = 0; nt < 4; nt++) {
                int n = wn + nt * 8 + lr;
                const float* p = Bb + n * SMS + ks * 8 + lc;
                b[nt][0] = __float_as_uint(p[0]);
                b[nt][1] = __float_as_uint(p[4]);
            }
            #pragma unroll
            for (int mt = 0; mt < 4; mt++)
                #pragma unroll
                for (int nt = 0; nt < 4; nt++)
                    mma_tf32(acc[mt][nt], a[mt], b[nt]);
        }
        __syncthreads();
    }

    // Epilogue: fragment c0/c1 at (row, col..col+1), c2/c3 at (row+8, ...)
    bool do_relu  = (flags & 1) != 0;
    bool do_round = (flags & 2) != 0;
    #pragma unroll
    for (int mt = 0; mt < 4; mt++) {
        int row = m0 + wm + mt * 16 + lr;
        #pragma unroll
        for (int nt = 0; nt < 4; nt++) {
            int col = n0 + wn + nt * 8 + lc * 2;
            float b0 = __ldg(&bias[col]), b1 = __ldg(&bias[col + 1]);
            #pragma unroll
            for (int half = 0; half < 2; half++) {
                int r = row + half * 8;
                float v0 = acc[mt][nt][half * 2 + 0] + b0;
                float v1 = acc[mt][nt][half * 2 + 1] + b1;
                if (res) {
                    const float* rp = res + (size_t)r * N + col;
                    v0 += rp[0]; v1 += rp[1];
                }
                if (do_relu)  { v0 = fmaxf(v0, 0.f); v1 = fmaxf(v1, 0.f); }
                if (do_round) { v0 = rtf32(v0); v1 = rtf32(v1); }
                *(float2*)(C + (size_t)r * N + col) = make_float2(v0, v1);
            }
        }
    }
}

// ---------------------------------------------------------------------------
// Round weights to tf32 (removes truncation bias in the MMA)
// ---------------------------------------------------------------------------
__global__ __launch_bounds__(256) void round_w_kernel(
    const float4* __restrict__ in, float4* __restrict__ out, int n4)
{
    int i = blockIdx.x * blockDim.x + threadIdx.x;
    if (i < n4) {
        float4 v = in[i];
        v.x = rtf32(v.x); v.y = rtf32(v.y); v.z = rtf32(v.z); v.w = rtf32(v.w);
        out[i] = v;
    }
}

// ---------------------------------------------------------------------------
// LayerNorm: one block per row of 1024, 256 threads; output tf32-rounded
// ---------------------------------------------------------------------------
__global__ __launch_bounds__(256) void ln_kernel(
    const float* __restrict__ x, const float* __restrict__ g,
    const float* __restrict__ bt, float* __restrict__ y)
{
    int row = blockIdx.x;
    int t = threadIdx.x;
    const float* xr = x + (size_t)row * DM;

    float4 v = *(const float4*)(xr + t * 4);
    float s  = v.x + v.y + v.z + v.w;
    float ss = v.x * v.x + v.y * v.y + v.z * v.z + v.w * v.w;

    #pragma unroll
    for (int o = 16; o; o >>= 1) {
        s  += __shfl_xor_sync(0xffffffffu, s,  o);
        ss += __shfl_xor_sync(0xffffffffu, ss, o);
    }
    __shared__ float rs[8], rss[8];
    if ((t & 31) == 0) { rs[t >> 5] = s; rss[t >> 5] = ss; }
    __syncthreads();
    if (t < 32) {
        float a  = (t < 8) ? rs[t]  : 0.f;
        float bb = (t < 8) ? rss[t] : 0.f;
        #pragma unroll
        for (int o = 4; o; o >>= 1) {
            a  += __shfl_xor_sync(0xffffffffu, a,  o);
            bb += __shfl_xor_sync(0xffffffffu, bb, o);
        }
        if (t == 0) { rs[0] = a; rss[0] = bb; }
    }
    __syncthreads();
    float mean = rs[0] * (1.f / DM);
    float var  = rss[0] * (1.f / DM) - mean * mean;
    float rstd = rsqrtf(var + 1e-5f);

    float4 gv = *(const float4*)(g  + t * 4);
    float4 bv = *(const float4*)(bt + t * 4);
    float4 ov;
    ov.x = rtf32((v.x - mean) * rstd * gv.x + bv.x);
    ov.y = rtf32((v.y - mean) * rstd * gv.y + bv.y);
    ov.z = rtf32((v.z - mean) * rstd * gv.z + bv.z);
    ov.w = rtf32((v.w - mean) * rstd * gv.w + bv.w);
    *(float4*)(y + (size_t)row * DM + t * 4) = ov;
}

// ---------------------------------------------------------------------------
// Flash-style attention with ALiBi-ish mask (SIMT fp32).
// Output tf32-rounded (feeds the out-proj MMA).
// ---------------------------------------------------------------------------
__global__ __launch_bounds__(256, 2) void attn_kernel(
    const float* __restrict__ qkv, float* __restrict__ o)
{
    __shared__ float Ks[64][68];   // K tile; reused to hold P
    __shared__ float Vs[64][68];

    int qt = blockIdx.x;
    int bh = blockIdx.y;
    int b  = bh >> 4;
    int h  = bh & 15;

    const float* base = qkv + ((size_t)b * SEQ) * (3 * DM) + h * DH;

    int t  = threadIdx.x;
    int r  = t >> 2;
    int c4 = t & 3;
    int iq = qt * 64 + r;

    float q[64];
    const float* qp = base + (size_t)iq * (3 * DM);
    #pragma unroll
    for (int d4 = 0; d4 < 16; d4++) {
        float4 v = *(const float4*)(qp + d4 * 4);
        q[d4 * 4 + 0] = v.x * 0.125f;
        q[d4 * 4 + 1] = v.y * 0.125f;
        q[d4 * 4 + 2] = v.z * 0.125f;
        q[d4 * 4 + 3] = v.w * 0.125f;
    }

    float m = -1e30f, l = 0.f;
    float oacc[16];
    #pragma unroll
    for (int i = 0; i < 16; i++) oacc[i] = 0.f;
    float slope = exp2f(-(float)h);

    for (int kt = 0; kt <= qt; kt++) {
        __syncthreads();
        #pragma unroll
        for (int e = 0; e < 4; e++) {
            int idx = t + 256 * e;
            int row = idx >> 4;
            int f4  = idx & 15;
            const float* kp = base + (size_t)(kt * 64 + row) * (3 * DM) + DM + f4 * 4;
            *(float4*)&Ks[row][f4 * 4] = *(const float4*)kp;
            *(float4*)&Vs[row][f4 * 4] = *(const float4*)(kp + DM);
        }
        __syncthreads();

        float p[16];
        float tmax = -1e30f;
        #pragma unroll
        for (int i = 0; i < 16; i++) {
            int c = 4 * i + c4;
            int j = kt * 64 + c;
            float s = 0.f;
            #pragma unroll
            for (int d4 = 0; d4 < 16; d4++) {
                float4 kv = *(const float4*)&Ks[c][d4 * 4];
                s += q[d4 * 4 + 0] * kv.x + q[d4 * 4 + 1] * kv.y
                   + q[d4 * 4 + 2] * kv.z + q[d4 * 4 + 3] * kv.w;
            }
            s -= (float)(iq + j) * slope;
            if (j > iq) s = -1e30f;
            p[i] = s;
            tmax = fmaxf(tmax, s);
        }
        tmax = fmaxf(tmax, __shfl_xor_sync(0xffffffffu, tmax, 1));
        tmax = fmaxf(tmax, __shfl_xor_sync(0xffffffffu, tmax, 2));

        float mnew = fmaxf(m, tmax);
        float corr = __expf(m - mnew);
        float psum = 0.f;
        #pragma unroll
        for (int i = 0; i < 16; i++) {
            p[i] = __expf(p[i] - mnew);
            psum += p[i];
        }
        psum += __shfl_xor_sync(0xffffffffu, psum, 1);
        psum += __shfl_xor_sync(0xffffffffu, psum, 2);
        l = l * corr + psum;
        m = mnew;
        #pragma unroll
        for (int i = 0; i < 16; i++) oacc[i] *= corr;

        __syncthreads();
        #pragma unroll
        for (int i = 0; i < 16; i++) Ks[r][4 * i + c4] = p[i];
        __syncthreads();

        #pragma unroll
        for (int j = 0; j < 64; j++) {
            float pv = Ks[r][j];
            #pragma unroll
            for (int db = 0; db < 4; db++) {
                float4 vv = *(const float4*)&Vs[j][c4 * 16 + db * 4];
                oacc[db * 4 + 0] += pv * vv.x;
                oacc[db * 4 + 1] += pv * vv.y;
                oacc[db * 4 + 2] += pv * vv.z;
                oacc[db * 4 + 3] += pv * vv.w;
            }
        }
    }

    float inv = 1.f / l;
    float* op = o + ((size_t)(b * SEQ) + iq) * DM + h * DH + c4 * 16;
    #pragma unroll
    for (int db = 0; db < 4; db++) {
        float4 ov;
        ov.x = rtf32(oacc[db * 4 + 0] * inv);
        ov.y = rtf32(oacc[db * 4 + 1] * inv);
        ov.z = rtf32(oacc[db * 4 + 2] * inv);
        ov.w = rtf32(oacc[db * 4 + 3] * inv);
        *(float4*)(op + db * 4) = ov;
    }
}

// ---------------------------------------------------------------------------
// Launch
// ---------------------------------------------------------------------------
#define GEMM_SMEM (4 * TILE_F * 4)   // 73728 bytes

extern "C" void kernel_launch(void* const* d_in, const int* in_sizes, int n_in,
                              void* d_out, int out_size)
{
    const float* src   = (const float*)d_in[0];
    const float* ln1_g = (const float*)d_in[1];
    const float* ln1_b = (const float*)d_in[2];
    const float* Wqkv  = (const float*)d_in[3];
    const float* bqkv  = (const float*)d_in[4];
    const float* Wout  = (const float*)d_in[5];
    const float* bout  = (const float*)d_in[6];
    const float* ln2_g = (const float*)d_in[7];
    const float* ln2_b = (const float*)d_in[8];
    const float* W1    = (const float*)d_in[9];
    const float* b1    = (const float*)d_in[10];
    const float* W2    = (const float*)d_in[11];
    const float* b2    = (const float*)d_in[12];
    float* out = (float*)d_out;

    float *h, *qkv, *o, *src2, *f, *ffn, *wq, *wo, *w1, *w2;
    cudaGetSymbolAddress((void**)&h,    g_h);
    cudaGetSymbolAddress((void**)&qkv,  g_qkv);
    cudaGetSymbolAddress((void**)&o,    g_o);
    cudaGetSymbolAddress((void**)&src2, g_src2);
    cudaGetSymbolAddress((void**)&f,    g_f);
    cudaGetSymbolAddress((void**)&ffn,  g_ffn);
    cudaGetSymbolAddress((void**)&wq,   g_wq);
    cudaGetSymbolAddress((void**)&wo,   g_wo);
    cudaGetSymbolAddress((void**)&w1,   g_w1);
    cudaGetSymbolAddress((void**)&w2,   g_w2);

    cudaFuncSetAttribute(mma_gemm, cudaFuncAttributeMaxDynamicSharedMemorySize, GEMM_SMEM);

    // 0) round weights to tf32
    round_w_kernel<<<(3 * DM * DM / 4 + 255) / 256, 256>>>((const float4*)Wqkv, (float4*)wq, 3 * DM * DM / 4);
    round_w_kernel<<<(DM * DM / 4 + 255) / 256, 256>>>((const float4*)Wout, (float4*)wo, DM * DM / 4);
    round_w_kernel<<<(DFF * DM / 4 + 255) / 256, 256>>>((const float4*)W1, (float4*)w1, DFF * DM / 4);
    round_w_kernel<<<(DM * DFF / 4 + 255) / 256, 256>>>((const float4*)W2, (float4*)w2, DM * DFF / 4);

    // 1) LN1 (tf32-rounded output)
    ln_kernel<<<MR, 256>>>(src, ln1_g, ln1_b, h);
    // 2) QKV = h @ Wqkv^T + bqkv   (rounded)
    mma_gemm<<<dim3(3 * DM / 128, MR / 128), 256, GEMM_SMEM>>>(
        h, wq, bqkv, nullptr, qkv, 3 * DM, DM, 2);
    // 3) attention -> o (rounded)
    attn_kernel<<<dim3(SEQ / 64, BB * NH), 256>>>(qkv, o);
    // 4) src2 = src + o @ Wout^T + bout  (full fp32)
    mma_gemm<<<dim3(DM / 128, MR / 128), 256, GEMM_SMEM>>>(
        o, wo, bout, src, src2, DM, DM, 0);
    // 5) LN2 (rounded)
    ln_kernel<<<MR, 256>>>(src2, ln2_g, ln2_b, f);
    // 6) ffn = relu(f @ W1^T + b1)  (rounded)
    mma_gemm<<<dim3(DFF / 128, MR / 128), 256, GEMM_SMEM>>>(
        f, w1, b1, nullptr, ffn, DFF, DM, 3);
    // 7) out = src2 + ffn @ W2^T + b2
    mma_gemm<<<dim3(DM / 128, MR / 128), 256, GEMM_SMEM>>>(
        ffn, w2, b2, src2, out, DM, DFF, 0);
}

// round 4
// speedup vs baseline: 4.4130x; 2.4910x over previous
#include <cuda_runtime.h>
#include <math.h>
#include <stdint.h>

// Problem constants
#define BB   2
#define SEQ  2048
#define DM   1024
#define NH   16
#define DH   64
#define DFF  4096
#define MR   (BB * SEQ)   // 4096 rows

// ---------------------------------------------------------------------------
// Scratch (no allocations allowed -> __device__ globals)
// ---------------------------------------------------------------------------
__device__ float g_h   [(size_t)MR * DM];        // LN1 output (tf32-rounded)
__device__ float g_qkv [(size_t)MR * 3 * DM];    // QKV projection (tf32-rounded)
__device__ float g_o   [(size_t)MR * DM];        // attention output (tf32-rounded)
__device__ float g_src2[(size_t)MR * DM];        // residual 1 (full fp32)
__device__ float g_f   [(size_t)MR * DM];        // LN2 output (tf32-rounded)
__device__ float g_ffn [(size_t)MR * DFF];       // FFN hidden (tf32-rounded)
__device__ float g_wq  [(size_t)3 * DM * DM];    // rounded Wqkv
__device__ float g_wo  [(size_t)DM * DM];        // rounded Wout
__device__ float g_w1  [(size_t)DFF * DM];       // rounded W1
__device__ float g_w2  [(size_t)DM * DFF];       // rounded W2

// ---------------------------------------------------------------------------
// Helpers
// ---------------------------------------------------------------------------
__device__ __forceinline__ uint32_t smem_u32(const void* p) {
    uint32_t a;
    asm("{ .reg .u64 t; cvta.to.shared.u64 t, %1; cvt.u32.u64 %0, t; }" : "=r"(a) : "l"(p));
    return a;
}
__device__ __forceinline__ float rtf32(float x) {
    uint32_t r;
    asm("cvt.rna.tf32.f32 %0, %1;" : "=r"(r) : "f"(x));
    return __uint_as_float(r);
}

#define CP16(dst, src) \
    asm volatile("cp.async.cg.shared.global [%0], [%1], 16;" :: "r"(dst), "l"(src) : "memory")
#define CP_COMMIT()  asm volatile("cp.async.commit_group;" ::: "memory")
#define CP_WAIT(n)   asm volatile("cp.async.wait_group %0;" :: "n"(n) : "memory")

__device__ __forceinline__ void mma_tf32(float* d, const uint32_t* a, const uint32_t* b) {
    asm volatile(
        "mma.sync.aligned.m16n8k8.row.col.f32.tf32.tf32.f32 "
        "{%0,%1,%2,%3}, {%4,%5,%6,%7}, {%8,%9}, {%0,%1,%2,%3};"
        : "+f"(d[0]), "+f"(d[1]), "+f"(d[2]), "+f"(d[3])
        : "r"(a[0]), "r"(a[1]), "r"(a[2]), "r"(a[3]), "r"(b[0]), "r"(b[1]));
}

// ---------------------------------------------------------------------------
// Tensor-core GEMM: C[M,N] = A[M,K] @ W[N,K]^T + bias (+res) (opt relu/round)
// 128x128 tile per CTA, BK=32, double-buffered cp.async, 256 threads.
// flags: 1 = relu, 2 = round output to tf32
// ---------------------------------------------------------------------------
#define SMS    36                 // smem row stride (floats)
#define TILE_F (128 * SMS)        // floats per (A or B) buffer

__global__ __launch_bounds__(256, 2) void mma_gemm(
    const float* __restrict__ A, const float* __restrict__ W,
    const float* __restrict__ bias, const float* __restrict__ res,
    float* __restrict__ C, int N, int K, int flags)
{
    extern __shared__ float sm[];
    float* As = sm;                 // [2][128][36]
    float* Bs = sm + 2 * TILE_F;    // [2][128][36]

    int t    = threadIdx.x;
    int wid  = t >> 5, lane = t & 31;
    int m0   = blockIdx.y * 128, n0 = blockIdx.x * 128;
    int wm   = (wid >> 2) * 64;
    int wn   = (wid & 3) * 32;
    int lr   = lane >> 2;
    int lc   = lane & 3;

    int tr = t >> 3, tc4 = (t & 7) * 4;
    const float* Ag = A + (size_t)(m0 + tr) * K + tc4;
    const float* Wg = W + (size_t)(n0 + tr) * K + tc4;
    uint32_t sA = smem_u32(As) + (uint32_t)((tr * SMS + tc4) * 4);
    uint32_t sB = smem_u32(Bs) + (uint32_t)((tr * SMS + tc4) * 4);
    const uint32_t rowStep = 32 * SMS * 4;
    const uint32_t bufStep = TILE_F * 4;

    float acc[4][4][4];
    #pragma unroll
    for (int i = 0; i < 4; i++)
        #pragma unroll
        for (int j = 0; j < 4; j++)
            #pragma unroll
            for (int k = 0; k < 4; k++) acc[i][j][k] = 0.f;

    int NK = K >> 5;

    #pragma unroll
    for (int i = 0; i < 4; i++) {
        CP16(sA + i * rowStep, Ag + (size_t)(32 * i) * K);
        CP16(sB + i * rowStep, Wg + (size_t)(32 * i) * K);
    }
    CP_COMMIT();

    for (int kt = 0; kt < NK; kt++) {
        int buf = kt & 1;
        if (kt + 1 < NK) {
            uint32_t off = (uint32_t)(buf ^ 1) * bufStep;
            const float* Ap = Ag + (size_t)(kt + 1) * 32;
            const float* Wp = Wg + (size_t)(kt + 1) * 32;
            #pragma unroll
            for (int i = 0; i < 4; i++) {
                CP16(sA + off + i * rowStep, Ap + (size_t)(32 * i) * K);
                CP16(sB + off + i * rowStep, Wp + (size_t)(32 * i) * K);
            }
            CP_COMMIT();
            CP_WAIT(1);
        } else {
            CP_WAIT(0);
        }
        __syncthreads();

        const float* Ab = As + buf * TILE_F;
        const float* Bb = Bs + buf * TILE_F;
        #pragma unroll
        for (int ks = 0; ks < 4; ks++) {
            uint32_t a[4][4], b[4][2];
            #pragma unroll
            for (int mt = 0; mt < 4; mt++) {
                int r = wm + mt * 16 + lr;
                const float* p = Ab + r * SMS + ks * 8 + lc;
                a[mt][0] = __float_as_uint(p[0]);
                a[mt][1] = __float_as_uint(p[8 * SMS]);
                a[mt][2] = __float_as_uint(p[4]);
                a[mt][3] = __float_as_uint(p[8 * SMS + 4]);
            }
            #pragma unroll
            for (int nt = 0; nt < 4; nt++) {
                int n = wn + nt * 8 + lr;
                const float* p = Bb + n * SMS + ks * 8 + lc;
                b[nt][0] = __float_as_uint(p[0]);
                b[nt][1] = __float_as_uint(p[4]);
            }
            #pragma unroll
            for (int mt = 0; mt < 4; mt++)
                #pragma unroll
                for (int nt = 0; nt < 4; nt++)
                    mma_tf32(acc[mt][nt], a[mt], b[nt]);
        }
        __syncthreads();
    }

    bool do_relu  = (flags & 1) != 0;
    bool do_round = (flags & 2) != 0;
    #pragma unroll
    for (int mt = 0; mt < 4; mt++) {
        int row = m0 + wm + mt * 16 + lr;
        #pragma unroll
        for (int nt = 0; nt < 4; nt++) {
            int col = n0 + wn + nt * 8 + lc * 2;
            float b0 = __ldg(&bias[col]), b1 = __ldg(&bias[col + 1]);
            #pragma unroll
            for (int half = 0; half < 2; half++) {
                int r = row + half * 8;
                float v0 = acc[mt][nt][half * 2 + 0] + b0;
                float v1 = acc[mt][nt][half * 2 + 1] + b1;
                if (res) {
                    const float* rp = res + (size_t)r * N + col;
                    v0 += rp[0]; v1 += rp[1];
                }
                if (do_relu)  { v0 = fmaxf(v0, 0.f); v1 = fmaxf(v1, 0.f); }
                if (do_round) { v0 = rtf32(v0); v1 = rtf32(v1); }
                *(float2*)(C + (size_t)r * N + col) = make_float2(v0, v1);
            }
        }
    }
}

// ---------------------------------------------------------------------------
// Round weights to tf32
// ---------------------------------------------------------------------------
__global__ __launch_bounds__(256) void round_w_kernel(
    const float4* __restrict__ in, float4* __restrict__ out, int n4)
{
    int i = blockIdx.x * blockDim.x + threadIdx.x;
    if (i < n4) {
        float4 v = in[i];
        v.x = rtf32(v.x); v.y = rtf32(v.y); v.z = rtf32(v.z); v.w = rtf32(v.w);
        out[i] = v;
    }
}

// ---------------------------------------------------------------------------
// LayerNorm: one block per row of 1024, 256 threads; output tf32-rounded
// ---------------------------------------------------------------------------
__global__ __launch_bounds__(256) void ln_kernel(
    const float* __restrict__ x, const float* __restrict__ g,
    const float* __restrict__ bt, float* __restrict__ y)
{
    int row = blockIdx.x;
    int t = threadIdx.x;
    const float* xr = x + (size_t)row * DM;

    float4 v = *(const float4*)(xr + t * 4);
    float s  = v.x + v.y + v.z + v.w;
    float ss = v.x * v.x + v.y * v.y + v.z * v.z + v.w * v.w;

    #pragma unroll
    for (int o = 16; o; o >>= 1) {
        s  += __shfl_xor_sync(0xffffffffu, s,  o);
        ss += __shfl_xor_sync(0xffffffffu, ss, o);
    }
    __shared__ float rs[8], rss[8];
    if ((t & 31) == 0) { rs[t >> 5] = s; rss[t >> 5] = ss; }
    __syncthreads();
    if (t < 32) {
        float a  = (t < 8) ? rs[t]  : 0.f;
        float bb = (t < 8) ? rss[t] : 0.f;
        #pragma unroll
        for (int o = 4; o; o >>= 1) {
            a  += __shfl_xor_sync(0xffffffffu, a,  o);
            bb += __shfl_xor_sync(0xffffffffu, bb, o);
        }
        if (t == 0) { rs[0] = a; rss[0] = bb; }
    }
    __syncthreads();
    float mean = rs[0] * (1.f / DM);
    float var  = rss[0] * (1.f / DM) - mean * mean;
    float rstd = rsqrtf(var + 1e-5f);

    float4 gv = *(const float4*)(g  + t * 4);
    float4 bv = *(const float4*)(bt + t * 4);
    float4 ov;
    ov.x = rtf32((v.x - mean) * rstd * gv.x + bv.x);
    ov.y = rtf32((v.y - mean) * rstd * gv.y + bv.y);
    ov.z = rtf32((v.z - mean) * rstd * gv.z + bv.z);
    ov.w = rtf32((v.w - mean) * rstd * gv.w + bv.w);
    *(float4*)(y + (size_t)row * DM + t * 4) = ov;
}

// ---------------------------------------------------------------------------
// Tensor-core flash attention with ALiBi-ish mask.
// One CTA = 128 q-rows of one (b,h). 8 warps x 16 rows. 64-key tiles,
// double-buffered cp.async. S and PV both on m16n8k8 tf32 MMA.
// ---------------------------------------------------------------------------
#define ATS 68                         // smem stride (floats)
#define KVB (64 * ATS)                 // floats per K or V buffer
#define ATTN_SMEM ((4 * KVB + 128 * ATS) * 4)   // 104448 bytes

__global__ __launch_bounds__(256, 2) void attn_mma(
    const float* __restrict__ qkv, float* __restrict__ o)
{
    extern __shared__ float sm[];
    float* KsB = sm;                   // [2][64][ATS]
    float* VsB = sm + 2 * KVB;         // [2][64][ATS]
    float* Ps  = sm + 4 * KVB;         // [128][ATS] (Q stage, then P)

    int qt = (int)gridDim.x - 1 - (int)blockIdx.x;   // heavy tiles first
    int bh = blockIdx.y;
    int b = bh >> 4, h = bh & 15;
    int t = threadIdx.x, wid = t >> 5, lane = t & 31;
    int lr = lane >> 2, lc = lane & 3;
    int q0 = qt * 128;
    int wr = wid * 16;
    float slope = exp2f(-(float)h);

    const float* base = qkv + (size_t)(b * SEQ) * (3 * DM) + h * DH;

    // ---- stage Q (x0.125) into Ps, pull fragments into registers
    {
        int r = t >> 1, cb = (t & 1) * 32;
        const float* qp = base + (size_t)(q0 + r) * (3 * DM) + cb;
        float* pp = Ps + r * ATS + cb;
        #pragma unroll
        for (int i = 0; i < 8; i++) {
            float4 v = *(const float4*)(qp + i * 4);
            v.x *= 0.125f; v.y *= 0.125f; v.z *= 0.125f; v.w *= 0.125f;
            *(float4*)(pp + i * 4) = v;
        }
    }
    __syncthreads();
    uint32_t qf[8][4];
    #pragma unroll
    for (int ks = 0; ks < 8; ks++) {
        const float* p = Ps + (wr + lr) * ATS + ks * 8 + lc;
        qf[ks][0] = __float_as_uint(p[0]);
        qf[ks][1] = __float_as_uint(p[8 * ATS]);
        qf[ks][2] = __float_as_uint(p[4]);
        qf[ks][3] = __float_as_uint(p[8 * ATS + 4]);
    }
    __syncthreads();

    float oacc[8][4];
    #pragma unroll
    for (int nt = 0; nt < 8; nt++)
        #pragma unroll
        for (int k = 0; k < 4; k++) oacc[nt][k] = 0.f;
    float m0 = -1e30f, m1 = -1e30f, l0 = 0.f, l1 = 0.f;
    int r0 = q0 + wr + lr, r1 = r0 + 8;

    int ktmax = 2 * qt + 1;

    // KV loader: each thread 4x cp.async(16B) per tensor
    int lv_r = t >> 2, lv_c = (t & 3) * 16;
    uint32_t ks_base = smem_u32(KsB) + (uint32_t)((lv_r * ATS + lv_c) * 4);
    uint32_t vs_base = smem_u32(VsB) + (uint32_t)((lv_r * ATS + lv_c) * 4);
    {
        const float* kp = base + (size_t)lv_r * (3 * DM) + DM + lv_c;
        #pragma unroll
        for (int i = 0; i < 4; i++) {
            CP16(ks_base + i * 16, kp + i * 4);
            CP16(vs_base + i * 16, kp + DM + i * 4);
        }
        CP_COMMIT();
    }

    for (int kt = 0; kt <= ktmax; kt++) {
        int buf = kt & 1;
        if (kt < ktmax) {
            uint32_t off = (uint32_t)((buf ^ 1) * KVB * 4);
            const float* kp = base + (size_t)((kt + 1) * 64 + lv_r) * (3 * DM) + DM + lv_c;
            #pragma unroll
            for (int i = 0; i < 4; i++) {
                CP16(ks_base + off + i * 16, kp + i * 4);
                CP16(vs_base + off + i * 16, kp + DM + i * 4);
            }
            CP_COMMIT();
            CP_WAIT(1);
        } else {
            CP_WAIT(0);
        }
        __syncthreads();

        const float* Kst = KsB + buf * KVB;
        const float* Vst = VsB + buf * KVB;

        // ---- S = Q K^T  (each warp: 16 rows x 64 cols)
        float sacc[8][4];
        #pragma unroll
        for (int nt = 0; nt < 8; nt++)
            #pragma unroll
            for (int k = 0; k < 4; k++) sacc[nt][k] = 0.f;
        #pragma unroll
        for (int ks = 0; ks < 8; ks++) {
            uint32_t bf[8][2];
            #pragma unroll
            for (int nt = 0; nt < 8; nt++) {
                const float* p = Kst + (nt * 8 + lr) * ATS + ks * 8 + lc;
                bf[nt][0] = __float_as_uint(p[0]);
                bf[nt][1] = __float_as_uint(p[4]);
            }
            #pragma unroll
            for (int nt = 0; nt < 8; nt++)
                mma_tf32(sacc[nt], qf[ks], bf[nt]);
        }

        // ---- mask + online softmax
        int jb = kt * 64;
        float rmax0 = -1e30f, rmax1 = -1e30f;
        #pragma unroll
        for (int nt = 0; nt < 8; nt++) {
            int j0 = jb + nt * 8 + 2 * lc;
            int j1 = j0 + 1;
            float s0 = sacc[nt][0] - (float)(r0 + j0) * slope;
            float s1 = sacc[nt][1] - (float)(r0 + j1) * slope;
            float s2 = sacc[nt][2] - (float)(r1 + j0) * slope;
            float s3 = sacc[nt][3] - (float)(r1 + j1) * slope;
            if (j0 > r0) s0 = -1e30f;
            if (j1 > r0) s1 = -1e30f;
            if (j0 > r1) s2 = -1e30f;
            if (j1 > r1) s3 = -1e30f;
            sacc[nt][0] = s0; sacc[nt][1] = s1; sacc[nt][2] = s2; sacc[nt][3] = s3;
            rmax0 = fmaxf(rmax0, fmaxf(s0, s1));
            rmax1 = fmaxf(rmax1, fmaxf(s2, s3));
        }
        rmax0 = fmaxf(rmax0, __shfl_xor_sync(0xffffffffu, rmax0, 1));
        rmax0 = fmaxf(rmax0, __shfl_xor_sync(0xffffffffu, rmax0, 2));
        rmax1 = fmaxf(rmax1, __shfl_xor_sync(0xffffffffu, rmax1, 1));
        rmax1 = fmaxf(rmax1, __shfl_xor_sync(0xffffffffu, rmax1, 2));

        float mn0 = fmaxf(m0, rmax0), mn1 = fmaxf(m1, rmax1);
        float c0 = __expf(m0 - mn0), c1 = __expf(m1 - mn1);
        m0 = mn0; m1 = mn1;

        float sum0 = 0.f, sum1 = 0.f;
        float* pr0 = Ps + (wr + lr) * ATS;
        float* pr1 = pr0 + 8 * ATS;
        #pragma unroll
        for (int nt = 0; nt < 8; nt++) {
            float e0 = __expf(sacc[nt][0] - mn0);
            float e1 = __expf(sacc[nt][1] - mn0);
            float e2 = __expf(sacc[nt][2] - mn1);
            float e3 = __expf(sacc[nt][3] - mn1);
            sum0 += e0 + e1; sum1 += e2 + e3;
            *(float2*)(pr0 + nt * 8 + 2 * lc) = make_float2(rtf32(e0), rtf32(e1));
            *(float2*)(pr1 + nt * 8 + 2 * lc) = make_float2(rtf32(e2), rtf32(e3));
            oacc[nt][0] *= c0; oacc[nt][1] *= c0;
            oacc[nt][2] *= c1; oacc[nt][3] *= c1;
        }
        sum0 += __shfl_xor_sync(0xffffffffu, sum0, 1);
        sum0 += __shfl_xor_sync(0xffffffffu, sum0, 2);
        sum1 += __shfl_xor_sync(0xffffffffu, sum1, 1);
        sum1 += __shfl_xor_sync(0xffffffffu, sum1, 2);
        l0 = l0 * c0 + sum0;
        l1 = l1 * c1 + sum1;
        __syncwarp();

        // ---- O += P V  (B frag reads V column-wise: conflict-free at stride 68)
        #pragma unroll
        for (int ks = 0; ks < 8; ks++) {
            uint32_t pa[4];
            const float* pp = Ps + (wr + lr) * ATS + ks * 8 + lc;
            pa[0] = __float_as_uint(pp[0]);
            pa[1] = __float_as_uint(pp[8 * ATS]);
            pa[2] = __float_as_uint(pp[4]);
            pa[3] = __float_as_uint(pp[8 * ATS + 4]);
            #pragma unroll
            for (int nt = 0; nt < 8; nt++) {
                uint32_t bv[2];
                const float* vp = Vst + (ks * 8 + lc) * ATS + nt * 8 + lr;
                bv[0] = __float_as_uint(vp[0]);
                bv[1] = __float_as_uint(vp[4 * ATS]);
                mma_tf32(oacc[nt], pa, bv);
            }
        }
        __syncthreads();   // all reads of this buf done before next prefetch
    }

    float inv0 = 1.f / l0, inv1 = 1.f / l1;
    float* op0 = o + (size_t)(b * SEQ + r0) * DM + h * DH;
    float* op1 = o + (size_t)(b * SEQ + r1) * DM + h * DH;
    #pragma unroll
    for (int nt = 0; nt < 8; nt++) {
        *(float2*)(op0 + nt * 8 + 2 * lc) =
            make_float2(rtf32(oacc[nt][0] * inv0), rtf32(oacc[nt][1] * inv0));
        *(float2*)(op1 + nt * 8 + 2 * lc) =
            make_float2(rtf32(oacc[nt][2] * inv1), rtf32(oacc[nt][3] * inv1));
    }
}

// ---------------------------------------------------------------------------
// Launch
// ---------------------------------------------------------------------------
#define GEMM_SMEM (4 * TILE_F * 4)   // 73728 bytes

extern "C" void kernel_launch(void* const* d_in, const int* in_sizes, int n_in,
                              void* d_out, int out_size)
{
    const float* src   = (const float*)d_in[0];
    const float* ln1_g = (const float*)d_in[1];
    const float* ln1_b = (const float*)d_in[2];
    const float* Wqkv  = (const float*)d_in[3];
    const float* bqkv  = (const float*)d_in[4];
    const float* Wout  = (const float*)d_in[5];
    const float* bout  = (const float*)d_in[6];
    const float* ln2_g = (const float*)d_in[7];
    const float* ln2_b = (const float*)d_in[8];
    const float* W1    = (const float*)d_in[9];
    const float* b1    = (const float*)d_in[10];
    const float* W2    = (const float*)d_in[11];
    const float* b2    = (const float*)d_in[12];
    float* out = (float*)d_out;

    float *h, *qkv, *o, *src2, *f, *ffn, *wq, *wo, *w1, *w2;
    cudaGetSymbolAddress((void**)&h,    g_h);
    cudaGetSymbolAddress((void**)&qkv,  g_qkv);
    cudaGetSymbolAddress((void**)&o,    g_o);
    cudaGetSymbolAddress((void**)&src2, g_src2);
    cudaGetSymbolAddress((void**)&f,    g_f);
    cudaGetSymbolAddress((void**)&ffn,  g_ffn);
    cudaGetSymbolAddress((void**)&wq,   g_wq);
    cudaGetSymbolAddress((void**)&wo,   g_wo);
    cudaGetSymbolAddress((void**)&w1,   g_w1);
    cudaGetSymbolAddress((void**)&w2,   g_w2);

    cudaFuncSetAttribute(mma_gemm, cudaFuncAttributeMaxDynamicSharedMemorySize, GEMM_SMEM);
    cudaFuncSetAttribute(attn_mma, cudaFuncAttributeMaxDynamicSharedMemorySize, ATTN_SMEM);

    // 0) round weights to tf32
    round_w_kernel<<<(3 * DM * DM / 4 + 255) / 256, 256>>>((const float4*)Wqkv, (float4*)wq, 3 * DM * DM / 4);
    round_w_kernel<<<(DM * DM / 4 + 255) / 256, 256>>>((const float4*)Wout, (float4*)wo, DM * DM / 4);
    round_w_kernel<<<(DFF * DM / 4 + 255) / 256, 256>>>((const float4*)W1, (float4*)w1, DFF * DM / 4);
    round_w_kernel<<<(DM * DFF / 4 + 255) / 256, 256>>>((const float4*)W2, (float4*)w2, DM * DFF / 4);

    // 1) LN1 (tf32-rounded output)
    ln_kernel<<<MR, 256>>>(src, ln1_g, ln1_b, h);
    // 2) QKV = h @ Wqkv^T + bqkv   (rounded -> attention operands are tf32)
    mma_gemm<<<dim3(3 * DM / 128, MR / 128), 256, GEMM_SMEM>>>(
        h, wq, bqkv, nullptr, qkv, 3 * DM, DM, 2);
    // 3) attention -> o (rounded)
    attn_mma<<<dim3(SEQ / 128, BB * NH), 256, ATTN_SMEM>>>(qkv, o);
    // 4) src2 = src + o @ Wout^T + bout  (full fp32)
    mma_gemm<<<dim3(DM / 128, MR / 128), 256, GEMM_SMEM>>>(
        o, wo, bout, src, src2, DM, DM, 0);
    // 5) LN2 (rounded)
    ln_kernel<<<MR, 256>>>(src2, ln2_g, ln2_b, f);
    // 6) ffn = relu(f @ W1^T + b1)  (rounded)
    mma_gemm<<<dim3(DFF / 128, MR / 128), 256, GEMM_SMEM>>>(
        f, w1, b1, nullptr, ffn, DFF, DM, 3);
    // 7) out = src2 + ffn @ W2^T + b2
    mma_gemm<<<dim3(DM / 128, MR / 128), 256, GEMM_SMEM>>>(
        ffn, w2, b2, src2, out, DM, DFF, 0);
}